// round 12
// baseline (speedup 1.0000x reference)
#include <cuda_runtime.h>

#define N_NODES 50000
#define N_EDGES 800000
#define N_FEAT  256
#define N_CLASS 64

typedef unsigned long long ull;

// ---------------- scratch (no allocation allowed -> device globals) ----------
__device__ int   g_cnt[N_NODES];
__device__ float g_dinv[N_NODES];
__device__ int   g_rowstart[N_NODES + 1];
__device__ int   g_cursor[N_NODES];
__device__ int   g_col[N_EDGES];
__device__ float g_val[N_EDGES];
__device__ float g_h0[(size_t)N_NODES * N_CLASS];
__device__ float g_h1[(size_t)N_NODES * N_CLASS];
__device__ int   g_idx64;

// ---------------- f32x2 packed math helpers (sm_103a FFMA2) ------------------
__device__ __forceinline__ ull pack2(float x, float y) {
    ull r;
    asm("mov.b64 %0, {%1, %2};" : "=l"(r) : "f"(x), "f"(y));
    return r;
}
__device__ __forceinline__ ull fma2(ull a, ull b, ull c) {
    ull d;
    asm("fma.rn.f32x2 %0, %1, %2, %3;" : "=l"(d) : "l"(a), "l"(b), "l"(c));
    return d;
}

// ---------------- int64-vs-int32 edge_index detector (warp-parallel) ---------
// int32 data read as int64 gives hi-word = random node id -> out of range with
// overwhelming probability within 256 samples. 8 parallel loads per lane.
__global__ void detect_kernel(const void* __restrict__ ei) {
    const long long* p = (const long long*)ei;
    int lane = threadIdx.x;
    int bad = 0;
    #pragma unroll
    for (int i = 0; i < 8; i++) {
        long long v = p[lane + i * 32];
        if (v < 0 || v >= N_NODES) bad = 1;
    }
    unsigned m = __ballot_sync(0xffffffffu, bad);
    if (lane == 0) g_idx64 = (m == 0) ? 1 : 0;
}

__device__ __forceinline__ int load_idx(const void* __restrict__ ei, long i) {
    if (g_idx64) return (int)((const long long*)ei)[i];
    return ((const int*)ei)[i];
}

// ---------------- preprocessing ----------------------------------------------
__global__ void zero_cnt_kernel() {
    int i = blockIdx.x * blockDim.x + threadIdx.x;
    if (i < N_NODES) g_cnt[i] = 0;
}

__global__ void count_kernel(const void* __restrict__ ei) {
    int e = blockIdx.x * blockDim.x + threadIdx.x;
    if (e < N_EDGES) {
        int d = load_idx(ei, (long)N_EDGES + e);
        atomicAdd(&g_cnt[d], 1);
    }
}

// one-block exclusive scan of g_cnt -> g_rowstart / g_cursor, fused with dinv
__global__ void scan_dinv_kernel() {
    __shared__ int part[1024];
    int t = threadIdx.x;
    const int SEG = (N_NODES + 1023) / 1024;  // 49
    int beg = t * SEG;
    int end = beg + SEG; if (end > N_NODES) end = N_NODES;
    int s = 0;
    for (int i = beg; i < end; i++) {
        int c = g_cnt[i];
        s += c;
        g_dinv[i] = rsqrtf((float)(c + 1));  // +1 self loop
    }
    part[t] = s;
    __syncthreads();
    for (int d = 1; d < 1024; d <<= 1) {
        int add = (t >= d) ? part[t - d] : 0;
        __syncthreads();
        part[t] += add;
        __syncthreads();
    }
    int off = (t == 0) ? 0 : part[t - 1];
    for (int i = beg; i < end; i++) {
        g_rowstart[i] = off;
        g_cursor[i]   = off;
        off += g_cnt[i];
    }
    if (t == 1023) g_rowstart[N_NODES] = part[1023];
}

__global__ void scatter_kernel(const void* __restrict__ ei) {
    int e = blockIdx.x * blockDim.x + threadIdx.x;
    if (e < N_EDGES) {
        int s = load_idx(ei, e);
        int d = load_idx(ei, (long)N_EDGES + e);
        int pos = atomicAdd(&g_cursor[d], 1);
        g_col[pos] = s;
        g_val[pos] = g_dinv[s] * g_dinv[d];
    }
}

// ---------------- GEMM: h0[50000,64] = X[50000,256] @ W[256,64] --------------
// block = 256 threads, tile 128 rows x 64 cols, BK = 16, thread tile 4x8,
// packed-pair accumulators via fma.rn.f32x2 (halves FMA instruction count).
#define BM 128
#define BK 16
__global__ __launch_bounds__(256) void gemm_kernel(
    const float* __restrict__ X, const float* __restrict__ W
) {
    __shared__ __align__(16) float As[BK][BM];   // [k][row]
    __shared__ __align__(16) float Bs[BK * 64];  // [k][col] (linear, matches W)
    int tid  = threadIdx.x;
    int row0 = blockIdx.x * BM;
    int ty = tid >> 3;   // 0..31 -> rows ty*4 .. ty*4+3
    int tx = tid & 7;    // 0..7  -> cols tx*8 .. tx*8+7

    ull acc[4][4] = {};  // [row][col-pair]; 0ULL == {+0.f,+0.f}

    // A-tile load mapping: two float4 along K per thread
    int lr = tid >> 1;          // 0..127 local row
    int lk = (tid & 1) * 8;     // 0 or 8
    int grow = row0 + lr;
    bool rvalid = grow < N_NODES;
    const float* xptr = X + (size_t)grow * N_FEAT + lk;

    for (int k0 = 0; k0 < N_FEAT; k0 += BK) {
        float4 x0 = make_float4(0.f, 0.f, 0.f, 0.f);
        float4 x1 = make_float4(0.f, 0.f, 0.f, 0.f);
        if (rvalid) {
            x0 = *(const float4*)(xptr + k0);
            x1 = *(const float4*)(xptr + k0 + 4);
        }
        As[lk + 0][lr] = x0.x; As[lk + 1][lr] = x0.y;
        As[lk + 2][lr] = x0.z; As[lk + 3][lr] = x0.w;
        As[lk + 4][lr] = x1.x; As[lk + 5][lr] = x1.y;
        As[lk + 6][lr] = x1.z; As[lk + 7][lr] = x1.w;
        // W chunk [k0..k0+16) x 64 = 1024 contiguous floats
        *(float4*)&Bs[tid * 4] = *(const float4*)&W[(size_t)k0 * 64 + tid * 4];
        __syncthreads();
        #pragma unroll
        for (int kk = 0; kk < BK; kk++) {
            float4 a = *(const float4*)&As[kk][ty * 4];
            float4 bA = *(const float4*)&Bs[kk * 64 + tx * 8];
            float4 bB = *(const float4*)&Bs[kk * 64 + tx * 8 + 4];
            ull b0 = pack2(bA.x, bA.y);
            ull b1 = pack2(bA.z, bA.w);
            ull b2 = pack2(bB.x, bB.y);
            ull b3 = pack2(bB.z, bB.w);
            ull pa0 = pack2(a.x, a.x);
            ull pa1 = pack2(a.y, a.y);
            ull pa2 = pack2(a.z, a.z);
            ull pa3 = pack2(a.w, a.w);
            acc[0][0] = fma2(pa0, b0, acc[0][0]);
            acc[0][1] = fma2(pa0, b1, acc[0][1]);
            acc[0][2] = fma2(pa0, b2, acc[0][2]);
            acc[0][3] = fma2(pa0, b3, acc[0][3]);
            acc[1][0] = fma2(pa1, b0, acc[1][0]);
            acc[1][1] = fma2(pa1, b1, acc[1][1]);
            acc[1][2] = fma2(pa1, b2, acc[1][2]);
            acc[1][3] = fma2(pa1, b3, acc[1][3]);
            acc[2][0] = fma2(pa2, b0, acc[2][0]);
            acc[2][1] = fma2(pa2, b1, acc[2][1]);
            acc[2][2] = fma2(pa2, b2, acc[2][2]);
            acc[2][3] = fma2(pa2, b3, acc[2][3]);
            acc[3][0] = fma2(pa3, b0, acc[3][0]);
            acc[3][1] = fma2(pa3, b1, acc[3][1]);
            acc[3][2] = fma2(pa3, b2, acc[3][2]);
            acc[3][3] = fma2(pa3, b3, acc[3][3]);
        }
        __syncthreads();
    }
    #pragma unroll
    for (int i = 0; i < 4; i++) {
        int r = row0 + ty * 4 + i;
        if (r < N_NODES) {
            ull* dst = (ull*)&g_h0[(size_t)r * 64 + tx * 8];
            dst[0] = acc[i][0];
            dst[1] = acc[i][1];
            dst[2] = acc[i][2];
            dst[3] = acc[i][3];
        }
    }
}

// ---------------- propagation hop: warp per node, float2 per lane ------------
// hout[n] = selfc(n)*hin[n] + sum_{e: dst==n} val[e]*hin[col[e]]  (+bias last)
__global__ __launch_bounds__(256) void hop_kernel(
    int sel_in, int sel_out, const float* __restrict__ bias, float* __restrict__ dout
) {
    int warp = (blockIdx.x * blockDim.x + threadIdx.x) >> 5;
    int lane = threadIdx.x & 31;
    if (warp >= N_NODES) return;
    int n = warp;

    const float* hin = (sel_in == 0) ? g_h0 : g_h1;
    float* hout = (sel_out == 0) ? g_h0 : ((sel_out == 1) ? g_h1 : dout);

    float di = g_dinv[n];
    float selfc = di * di;

    const float2* hin2 = (const float2*)hin;
    float2 hv = hin2[(size_t)n * 32 + lane];
    float2 acc = make_float2(selfc * hv.x, selfc * hv.y);

    int start = g_rowstart[n];
    int end   = g_rowstart[n + 1];
    for (int base = start; base < end; base += 32) {
        int idx = base + lane;
        int c = 0; float w = 0.f;
        if (idx < end) { c = g_col[idx]; w = g_val[idx]; }
        int m = end - base; if (m > 32) m = 32;
        #pragma unroll 4
        for (int j = 0; j < m; j++) {
            int   s  = __shfl_sync(0xffffffffu, c, j);
            float ww = __shfl_sync(0xffffffffu, w, j);
            float2 v = hin2[(size_t)s * 32 + lane];
            acc.x = fmaf(ww, v.x, acc.x);
            acc.y = fmaf(ww, v.y, acc.y);
        }
    }
    if (bias) {
        float2 bb = ((const float2*)bias)[lane];
        acc.x += bb.x;
        acc.y += bb.y;
    }
    ((float2*)hout)[(size_t)n * 32 + lane] = acc;
}

// ---------------- launch ------------------------------------------------------
extern "C" void kernel_launch(void* const* d_in, const int* in_sizes, int n_in,
                              void* d_out, int out_size) {
    const float* x  = (const float*)d_in[0];
    const void*  ei = d_in[1];
    const float* W  = (const float*)d_in[2];
    const float* b  = (const float*)d_in[3];
    float* out = (float*)d_out;

    const int TB = 256;
    detect_kernel<<<1, 32>>>(ei);
    zero_cnt_kernel<<<(N_NODES + TB - 1) / TB, TB>>>();
    count_kernel<<<(N_EDGES + TB - 1) / TB, TB>>>(ei);
    scan_dinv_kernel<<<1, 1024>>>();
    scatter_kernel<<<(N_EDGES + TB - 1) / TB, TB>>>(ei);

    // project first (S^3 x) W == S^3 (x W): 4x less hop traffic
    gemm_kernel<<<(N_NODES + BM - 1) / BM, TB>>>(x, W);

    int hop_blocks = (N_NODES * 32 + TB - 1) / TB;  // warp per node
    hop_kernel<<<hop_blocks, TB>>>(0, 1, nullptr, nullptr);
    hop_kernel<<<hop_blocks, TB>>>(1, 0, nullptr, nullptr);
    hop_kernel<<<hop_blocks, TB>>>(0, 2, b, out);
}